// round 12
// baseline (speedup 1.0000x reference)
#include <cuda_runtime.h>
#include <cuda_fp16.h>
#include <cstdint>

#define DIM 512
#define TMt 128
#define TNt 128
#define NKC 8                       // K chunks of 64
#define APITCH 68                   // f32 per A row (64 + 4 pad) -> 272B
#define A_STAGE_BYTES (128 * APITCH * 4)   // 34816
#define B_STAGE_BYTES 16384                // 128 rows x 64 halves x 2B
#define SMEM_BYTES (2 * A_STAGE_BYTES + 2 * B_STAGE_BYTES)   // 102400

// S = A + A^T in fp16; 512 KB, L2-resident during GEMM
__device__ __half g_Sh[DIM * DIM];

__global__ void prep_S(const float* __restrict__ A) {
    int i = blockIdx.x * 256 + threadIdx.x;   // 262144
    int e = i >> 9, d = i & 511;
    g_Sh[i] = __float2half(A[i] + A[d * DIM + e]);
}

// ---------------- helpers ----------------
__device__ __forceinline__ uint32_t smem_u32(const void* p) {
    return (uint32_t)__cvta_generic_to_shared(p);
}
__device__ __forceinline__ void cpa16(uint32_t dst, const void* src) {
    asm volatile("cp.async.cg.shared.global [%0], [%1], 16;" :: "r"(dst), "l"(src) : "memory");
}
__device__ __forceinline__ void ldm4(uint32_t* r, uint32_t addr) {
    asm volatile("ldmatrix.sync.aligned.m8n8.x4.shared.b16 {%0,%1,%2,%3}, [%4];"
                 : "=r"(r[0]), "=r"(r[1]), "=r"(r[2]), "=r"(r[3]) : "r"(addr));
}
__device__ __forceinline__ uint32_t packh2(float x, float y) {
    __half2 h = __floats2half2_rn(x, y);      // lo = x, hi = y
    return *reinterpret_cast<uint32_t*>(&h);
}
__device__ __forceinline__ void mma16816(float* d, const uint32_t* a, uint32_t b0, uint32_t b1) {
    asm volatile(
        "mma.sync.aligned.m16n8k16.row.col.f32.f16.f16.f32 "
        "{%0,%1,%2,%3}, {%4,%5,%6,%7}, {%8,%9}, {%0,%1,%2,%3};"
        : "+f"(d[0]), "+f"(d[1]), "+f"(d[2]), "+f"(d[3])
        : "r"(a[0]), "r"(a[1]), "r"(a[2]), "r"(a[3]), "r"(b0), "r"(b1));
}

// ---------------- main fused kernel ----------------
// out[:, 0:512]    = p + q @ S   (A operand: q fp32 staged in SMEM, cvt to fp16 at frag build)
// out[:, 512:1024] = q           (streamed from the same SMEM stages; zero extra reads)
__global__ void __launch_bounds__(256, 2)
gemm_fused(const float* __restrict__ pq, float* __restrict__ out) {
    extern __shared__ __align__(1024) char smem_raw[];
    const uint32_t sA = smem_u32(smem_raw);                 // 2 A stages (fp32)
    const uint32_t sB = sA + 2 * A_STAGE_BYTES;             // 2 B stages (fp16, swizzled)

    const int tid = threadIdx.x;
    const int wid = tid >> 5, lane = tid & 31;
    const int wm = wid & 3, wn = wid >> 2;                  // 4(m) x 2(n); warp tile 32x64
    const int l4 = lane >> 2, lc = lane & 3;
    const int bx = blockIdx.x;
    const int m0 = (bx >> 2) * TMt;
    const int n0 = (bx & 3) * TNt;
    const int jmatch = n0 >> 7;                             // q-copy chunks 2j, 2j+1

    // B ldmatrix lane-address components
    const int sw = lane & 7;
    const int rowB = wn * 64 + (lane & 7) + ((lane >> 4) & 1) * 8;   // + pair*16
    const int hiB = (lane >> 3) & 1;

    // A fragment rows (fp32 SMEM)
    const int rowA0 = wm * 32 + l4;                          // + mf*16 (+8 for a1/a3)

    // issue cp.async for K-chunk kc into stage kc%2
    auto issue = [&](int kc) {
        const uint32_t as = sA + (kc & 1) * A_STAGE_BYTES;
        const uint32_t bs = sB + (kc & 1) * B_STAGE_BYTES;
        const float* qs = pq + (size_t)m0 * 1024 + DIM + kc * 64;
        #pragma unroll
        for (int t = 0; t < 8; t++) {                        // A: 2048 x 16B (fp32)
            int i = tid + t * 256;
            int r = i >> 4, c = i & 15;
            cpa16(as + r * 272 + c * 16, qs + (size_t)r * 1024 + c * 4);
        }
        const __half* ss = g_Sh + (size_t)n0 * DIM + kc * 64;
        #pragma unroll
        for (int t = 0; t < 4; t++) {                        // B: 1024 x 16B (fp16, swizzled)
            int i = tid + t * 256;
            int r = i >> 3, c = i & 7;
            uint32_t off = r * 128 + ((c ^ (r & 7)) << 4);
            cpa16(bs + off, ss + (size_t)r * DIM + c * 8);
        }
        asm volatile("cp.async.commit_group;" ::: "memory");
    };

    issue(0);

    float d[2][8][4];
    #pragma unroll
    for (int i = 0; i < 2; i++)
        #pragma unroll
        for (int j = 0; j < 8; j++)
            #pragma unroll
            for (int k = 0; k < 4; k++) d[i][j][k] = 0.f;

    for (int kc = 0; kc < NKC; kc++) {
        asm volatile("cp.async.wait_group 0;" ::: "memory");  // chunk kc landed (this thread)
        __syncthreads();                                      // visible to all; prev stage free

        if (kc + 1 < NKC) issue(kc + 1);

        const uint32_t as = sA + (kc & 1) * A_STAGE_BYTES;
        const uint32_t bs = sB + (kc & 1) * B_STAGE_BYTES;

        // q-copy: this CTA's output cols [n0, n0+128) == chunks 2j, 2j+1; stream from SMEM
        if ((kc >> 1) == jmatch) {
            float* o = out + (size_t)m0 * 1024 + DIM + kc * 64;
            #pragma unroll
            for (int t = 0; t < 8; t++) {
                int i = tid + t * 256;
                int r = i >> 4, c = i & 15;
                float4 v;
                asm volatile("ld.shared.v4.f32 {%0,%1,%2,%3}, [%4];"
                             : "=f"(v.x), "=f"(v.y), "=f"(v.z), "=f"(v.w)
                             : "r"(as + r * 272 + c * 16));
                *reinterpret_cast<float4*>(o + (size_t)r * 1024 + c * 4) = v;
            }
        }

        #pragma unroll
        for (int s = 0; s < 4; s++) {
            const int k = s * 16;
            uint32_t a[2][4];
            #pragma unroll
            for (int mf = 0; mf < 2; mf++) {
                const uint32_t base = as + (rowA0 + mf * 16) * 272 + (k + 2 * lc) * 4;
                float2 v0, v1, v2, v3;
                asm volatile("ld.shared.v2.f32 {%0,%1}, [%2];" : "=f"(v0.x), "=f"(v0.y) : "r"(base));
                asm volatile("ld.shared.v2.f32 {%0,%1}, [%2];" : "=f"(v1.x), "=f"(v1.y) : "r"(base + 8 * 272));
                asm volatile("ld.shared.v2.f32 {%0,%1}, [%2];" : "=f"(v2.x), "=f"(v2.y) : "r"(base + 32));
                asm volatile("ld.shared.v2.f32 {%0,%1}, [%2];" : "=f"(v3.x), "=f"(v3.y) : "r"(base + 8 * 272 + 32));
                a[mf][0] = packh2(v0.x, v0.y);
                a[mf][1] = packh2(v1.x, v1.y);
                a[mf][2] = packh2(v2.x, v2.y);
                a[mf][3] = packh2(v3.x, v3.y);
            }
            #pragma unroll
            for (int p = 0; p < 4; p++) {
                uint32_t b[4];
                ldm4(b, bs + (rowB + p * 16) * 128 + (((2 * s + hiB) ^ sw) << 4));
                mma16816(d[0][2 * p + 0], a[0], b[0], b[1]);
                mma16816(d[0][2 * p + 1], a[0], b[2], b[3]);
                mma16816(d[1][2 * p + 0], a[1], b[0], b[1]);
                mma16816(d[1][2 * p + 1], a[1], b[2], b[3]);
            }
        }
    }

    // ---- epilogue: out[:, n0 + c] = p + pterm
    #pragma unroll
    for (int mf = 0; mf < 2; mf++) {
        #pragma unroll
        for (int rh = 0; rh < 2; rh++) {
            int row = m0 + wm * 32 + mf * 16 + rh * 8 + l4;
            const float* pr = pq + (size_t)row * 1024 + n0 + wn * 64 + 2 * lc;
            float* orow = out + (size_t)row * 1024 + n0 + wn * 64 + 2 * lc;
            #pragma unroll
            for (int nf = 0; nf < 8; nf++) {
                float2 pv = *reinterpret_cast<const float2*>(pr + nf * 8);
                float2 ov;
                ov.x = pv.x + d[mf][nf][rh * 2 + 0];
                ov.y = pv.y + d[mf][nf][rh * 2 + 1];
                *reinterpret_cast<float2*>(orow + nf * 8) = ov;
            }
        }
    }
}

extern "C" void kernel_launch(void* const* d_in, const int* in_sizes, int n_in,
                              void* d_out, int out_size) {
    const float* pq = (const float*)d_in[0];
    const float* A  = (const float*)d_in[1];
    if (n_in >= 2 && in_sizes[0] == DIM * DIM) {   // defensive: swap if order differs
        A  = (const float*)d_in[0];
        pq = (const float*)d_in[1];
    }
    float* out = (float*)d_out;

    cudaFuncSetAttribute(gemm_fused, cudaFuncAttributeMaxDynamicSharedMemorySize, SMEM_BYTES);
    prep_S<<<(DIM * DIM) / 256, 256>>>(A);
    gemm_fused<<<(65536 / TMt) * (DIM / TNt), 256, SMEM_BYTES>>>(pq, out);
}

// round 13
// speedup vs baseline: 1.3330x; 1.3330x over previous
#include <cuda_runtime.h>
#include <cuda_fp16.h>
#include <cstdint>

#define DIM 512
#define TMt 128
#define TNt 128
#define NKC 8                       // K chunks of 64
#define STAGE_BYTES 16384           // 128 rows x 64 halves x 2B
#define SMEM_BYTES (2 * STAGE_BYTES + 3 * STAGE_BYTES)   // A x2 + B x3 = 81920

// S = A + A^T in fp16; 512 KB, L2-resident during GEMM
__device__ __half g_Sh[DIM * DIM];

__global__ void prep_S(const float* __restrict__ A) {
    int i = blockIdx.x * 256 + threadIdx.x;   // 262144
    int e = i >> 9, d = i & 511;
    g_Sh[i] = __float2half(A[i] + A[d * DIM + e]);
}

// ---------------- helpers ----------------
__device__ __forceinline__ uint32_t smem_u32(const void* p) {
    return (uint32_t)__cvta_generic_to_shared(p);
}
__device__ __forceinline__ void cpa16(uint32_t dst, const void* src) {
    asm volatile("cp.async.cg.shared.global [%0], [%1], 16;" :: "r"(dst), "l"(src) : "memory");
}
__device__ __forceinline__ void ldm4(uint32_t* r, uint32_t addr) {
    asm volatile("ldmatrix.sync.aligned.m8n8.x4.shared.b16 {%0,%1,%2,%3}, [%4];"
                 : "=r"(r[0]), "=r"(r[1]), "=r"(r[2]), "=r"(r[3]) : "r"(addr));
}
__device__ __forceinline__ uint32_t packh2(float x, float y) {
    __half2 h = __floats2half2_rn(x, y);      // lo = x, hi = y
    return *reinterpret_cast<uint32_t*>(&h);
}
__device__ __forceinline__ void mma16816(float* d, const uint32_t* a, uint32_t b0, uint32_t b1) {
    asm volatile(
        "mma.sync.aligned.m16n8k16.row.col.f32.f16.f16.f32 "
        "{%0,%1,%2,%3}, {%4,%5,%6,%7}, {%8,%9}, {%0,%1,%2,%3};"
        : "+f"(d[0]), "+f"(d[1]), "+f"(d[2]), "+f"(d[3])
        : "r"(a[0]), "r"(a[1]), "r"(a[2]), "r"(a[3]), "r"(b0), "r"(b1));
}

// ---------------- main fused kernel ----------------
// out[:, 0:512]    = p + q @ S   (q read ONCE: LDG -> regs -> {STG q-copy, cvt+STS A})
// out[:, 512:1024] = q
__global__ void __launch_bounds__(256, 2)
gemm_fused(const float* __restrict__ pq, float* __restrict__ out) {
    extern __shared__ __align__(1024) char smem_raw[];
    const uint32_t sA = smem_u32(smem_raw);                 // 2 A stages (fp16, swizzled)
    const uint32_t sB = sA + 2 * STAGE_BYTES;               // 3 B stages (fp16, swizzled)

    const int tid = threadIdx.x;
    const int wid = tid >> 5, lane = tid & 31;
    const int wm = wid & 3, wn = wid >> 2;                  // 4(m) x 2(n); warp tile 32x64
    const int l4 = lane >> 2, lc = lane & 3;
    const int bx = blockIdx.x;
    const int m0 = (bx >> 2) * TMt;
    const int n0 = (bx & 3) * TNt;
    const int jmatch = n0 >> 7;                             // q-copy chunks 2j, 2j+1

    // ldmatrix lane-address components (identical layout for A and B stages)
    const int sw = lane & 7;
    const int rowA = wm * 32 + (lane & 7) + ((lane >> 3) & 1) * 8;   // + mf*16
    const int hiA = (lane >> 4) & 1;
    const int rowB = wn * 64 + (lane & 7) + ((lane >> 4) & 1) * 8;   // + pair*16
    const int hiB = (lane >> 3) & 1;

    // per-thread q slice coords: i = tid + t*256 -> row i>>4, 4-float col (i&15)*4
    const int qr = tid >> 4;            // rows qr, qr+16, ... (t*16)
    const int qc = tid & 15;            // 4-float granule within 64-col chunk

    // B issue: cp.async chunk kc into stage kc%3
    auto issueB = [&](int kc) {
        const uint32_t bs = sB + (kc % 3) * STAGE_BYTES;
        const __half* ss = g_Sh + (size_t)n0 * DIM + kc * 64;
        #pragma unroll
        for (int t = 0; t < 4; t++) {
            int i = tid + t * 256;
            int r = i >> 3, c = i & 7;
            uint32_t off = r * 128 + ((c ^ (r & 7)) << 4);
            cpa16(bs + off, ss + (size_t)r * DIM + c * 8);
        }
        asm volatile("cp.async.commit_group;" ::: "memory");
    };

    float4 qreg[8];
    auto ldgQ = [&](int kc) {
        const float* qs = pq + (size_t)m0 * 1024 + DIM + kc * 64;
        #pragma unroll
        for (int t = 0; t < 8; t++)
            qreg[t] = *reinterpret_cast<const float4*>(qs + (size_t)(qr + t * 16) * 1024 + qc * 4);
    };
    // STS A chunk (held in qreg) into stage kc&1; optionally STG the q-copy
    auto stsA = [&](int kc) {
        const uint32_t as = sA + (kc & 1) * STAGE_BYTES;
        const bool match = (kc >> 1) == jmatch;
        float* qo = out + (size_t)m0 * 1024 + DIM + kc * 64;
        #pragma unroll
        for (int t = 0; t < 8; t++) {
            int r = qr + t * 16;
            uint32_t h0 = packh2(qreg[t].x, qreg[t].y);
            uint32_t h1 = packh2(qreg[t].z, qreg[t].w);
            uint32_t off = r * 128 + ((((qc >> 1) ^ (r & 7)) << 4) | ((qc & 1) << 3));
            asm volatile("st.shared.v2.b32 [%0], {%1, %2};" :: "r"(as + off), "r"(h0), "r"(h1) : "memory");
            if (match)
                *reinterpret_cast<float4*>(qo + (size_t)r * 1024 + qc * 4) = qreg[t];
        }
    };

    // ---- prologue
    ldgQ(0);
    issueB(0); issueB(1);
    stsA(0);
    ldgQ(1);

    float d[2][8][4];
    #pragma unroll
    for (int i = 0; i < 2; i++)
        #pragma unroll
        for (int j = 0; j < 8; j++)
            #pragma unroll
            for (int k = 0; k < 4; k++) d[i][j][k] = 0.f;

    for (int kc = 0; kc < NKC; kc++) {
        asm volatile("cp.async.wait_group 1;" ::: "memory");   // B chunk kc landed
        __syncthreads();                                       // A(kc) STS visible; stages fenced

        if (kc + 2 < NKC) issueB(kc + 2);
        else asm volatile("cp.async.commit_group;" ::: "memory");

        // A pipeline: store chunk kc+1 (in regs), prefetch chunk kc+2
        if (kc + 1 < NKC) {
            stsA(kc + 1);
            if (kc + 2 < NKC) ldgQ(kc + 2);
        }

        const uint32_t as = sA + (kc & 1) * STAGE_BYTES;
        const uint32_t bs = sB + (kc % 3) * STAGE_BYTES;

        #pragma unroll
        for (int s = 0; s < 4; s++) {
            uint32_t a[2][4];
            #pragma unroll
            for (int mf = 0; mf < 2; mf++)
                ldm4(a[mf], as + (rowA + mf * 16) * 128 + (((2 * s + hiA) ^ sw) << 4));
            #pragma unroll
            for (int p = 0; p < 4; p++) {
                uint32_t b[4];
                ldm4(b, bs + (rowB + p * 16) * 128 + (((2 * s + hiB) ^ sw) << 4));
                mma16816(d[0][2 * p + 0], a[0], b[0], b[1]);
                mma16816(d[0][2 * p + 1], a[0], b[2], b[3]);
                mma16816(d[1][2 * p + 0], a[1], b[0], b[1]);
                mma16816(d[1][2 * p + 1], a[1], b[2], b[3]);
            }
        }
    }

    // ---- epilogue: out[:, n0 + c] = p + pterm
    #pragma unroll
    for (int mf = 0; mf < 2; mf++) {
        #pragma unroll
        for (int rh = 0; rh < 2; rh++) {
            int row = m0 + wm * 32 + mf * 16 + rh * 8 + l4;
            const float* pr = pq + (size_t)row * 1024 + n0 + wn * 64 + 2 * lc;
            float* orow = out + (size_t)row * 1024 + n0 + wn * 64 + 2 * lc;
            #pragma unroll
            for (int nf = 0; nf < 8; nf++) {
                float2 pv = *reinterpret_cast<const float2*>(pr + nf * 8);
                float2 ov;
                ov.x = pv.x + d[mf][nf][rh * 2 + 0];
                ov.y = pv.y + d[mf][nf][rh * 2 + 1];
                *reinterpret_cast<float2*>(orow + nf * 8) = ov;
            }
        }
    }
}

extern "C" void kernel_launch(void* const* d_in, const int* in_sizes, int n_in,
                              void* d_out, int out_size) {
    const float* pq = (const float*)d_in[0];
    const float* A  = (const float*)d_in[1];
    if (n_in >= 2 && in_sizes[0] == DIM * DIM) {   // defensive: swap if order differs
        A  = (const float*)d_in[0];
        pq = (const float*)d_in[1];
    }
    float* out = (float*)d_out;

    cudaFuncSetAttribute(gemm_fused, cudaFuncAttributeMaxDynamicSharedMemorySize, SMEM_BYTES);
    prep_S<<<(DIM * DIM) / 256, 256>>>(A);
    gemm_fused<<<(65536 / TMt) * (DIM / TNt), 256, SMEM_BYTES>>>(pq, out);
}

// round 14
// speedup vs baseline: 1.4466x; 1.0852x over previous
#include <cuda_runtime.h>
#include <cuda_fp16.h>
#include <cstdint>

#define DIM 512
#define TMt 128
#define TNt 128
#define NKC 8                       // K chunks of 64
#define STAGE_BYTES 16384           // 128 rows x 64 halves x 2B
#define SMEM_BYTES (2 * STAGE_BYTES + 3 * STAGE_BYTES)   // A x2 + B x3 = 81920

// S = A + A^T in fp16; 512 KB, L2-resident during GEMM
__device__ __half g_Sh[DIM * DIM];

__global__ void prep_S(const float* __restrict__ A) {
    int i = blockIdx.x * 256 + threadIdx.x;   // 262144
    int e = i >> 9, d = i & 511;
    g_Sh[i] = __float2half(A[i] + A[d * DIM + e]);
}

// ---------------- helpers ----------------
__device__ __forceinline__ uint32_t smem_u32(const void* p) {
    return (uint32_t)__cvta_generic_to_shared(p);
}
__device__ __forceinline__ void cpa16(uint32_t dst, const void* src) {
    asm volatile("cp.async.cg.shared.global [%0], [%1], 16;" :: "r"(dst), "l"(src) : "memory");
}
__device__ __forceinline__ void ldm4(uint32_t* r, uint32_t addr) {
    asm volatile("ldmatrix.sync.aligned.m8n8.x4.shared.b16 {%0,%1,%2,%3}, [%4];"
                 : "=r"(r[0]), "=r"(r[1]), "=r"(r[2]), "=r"(r[3]) : "r"(addr));
}
__device__ __forceinline__ uint32_t packh2(float x, float y) {
    __half2 h = __floats2half2_rn(x, y);      // lo = x, hi = y
    return *reinterpret_cast<uint32_t*>(&h);
}
__device__ __forceinline__ void mma16816(float* d, const uint32_t* a, uint32_t b0, uint32_t b1) {
    asm volatile(
        "mma.sync.aligned.m16n8k16.row.col.f32.f16.f16.f32 "
        "{%0,%1,%2,%3}, {%4,%5,%6,%7}, {%8,%9}, {%0,%1,%2,%3};"
        : "+f"(d[0]), "+f"(d[1]), "+f"(d[2]), "+f"(d[3])
        : "r"(a[0]), "r"(a[1]), "r"(a[2]), "r"(a[3]), "r"(b0), "r"(b1));
}

// ---------------- main fused kernel ----------------
// out[:, 0:512]    = p + q @ S   (q read ONCE: LDG -> regs -> {STG q-copy, cvt+STS A})
// out[:, 512:1024] = q
__global__ void __launch_bounds__(256, 2)
gemm_fused(const float* __restrict__ pq, float* __restrict__ out) {
    extern __shared__ __align__(1024) char smem_raw[];
    const uint32_t sA = smem_u32(smem_raw);                 // 2 A stages (fp16, swizzled)
    const uint32_t sB = sA + 2 * STAGE_BYTES;               // 3 B stages (fp16, swizzled)

    const int tid = threadIdx.x;
    const int wid = tid >> 5, lane = tid & 31;
    const int wm = wid & 3, wn = wid >> 2;                  // 4(m) x 2(n); warp tile 32x64
    const int l4 = lane >> 2, lc = lane & 3;
    const int bx = blockIdx.x;
    const int m0 = (bx >> 2) * TMt;
    const int n0 = (bx & 3) * TNt;
    const int jmatch = n0 >> 7;                             // q-copy chunks 2j, 2j+1

    // ldmatrix lane-address components (identical layout for A and B stages)
    const int sw = lane & 7;
    const int rowA = wm * 32 + (lane & 7) + ((lane >> 3) & 1) * 8;   // + mf*16
    const int hiA = (lane >> 4) & 1;
    const int rowB = wn * 64 + (lane & 7) + ((lane >> 4) & 1) * 8;   // + pair*16
    const int hiB = (lane >> 3) & 1;

    // per-thread q slice coords: row qr + (t + 4h)*16, 4-float granule qc
    const int qr = tid >> 4;
    const int qc = tid & 15;

    // B issue: cp.async chunk kc into stage kc%3
    auto issueB = [&](int kc) {
        const uint32_t bs = sB + (kc % 3) * STAGE_BYTES;
        const __half* ss = g_Sh + (size_t)n0 * DIM + kc * 64;
        #pragma unroll
        for (int t = 0; t < 4; t++) {
            int i = tid + t * 256;
            int r = i >> 3, c = i & 7;
            uint32_t off = r * 128 + ((c ^ (r & 7)) << 4);
            cpa16(bs + off, ss + (size_t)r * DIM + c * 8);
        }
        asm volatile("cp.async.commit_group;" ::: "memory");
    };

    float4 qreg[4];                                          // single 16-reg relay bank
    auto ldgQ = [&](int kc, int h) {
        const float* qs = pq + (size_t)m0 * 1024 + DIM + kc * 64;
        #pragma unroll
        for (int t = 0; t < 4; t++)
            qreg[t] = *reinterpret_cast<const float4*>(
                qs + (size_t)(qr + (t + 4 * h) * 16) * 1024 + qc * 4);
    };
    auto stsA = [&](int kc, int h) {
        const uint32_t as = sA + (kc & 1) * STAGE_BYTES;
        const bool match = (kc >> 1) == jmatch;
        float* qo = out + (size_t)m0 * 1024 + DIM + kc * 64;
        #pragma unroll
        for (int t = 0; t < 4; t++) {
            int r = qr + (t + 4 * h) * 16;
            uint32_t h0 = packh2(qreg[t].x, qreg[t].y);
            uint32_t h1 = packh2(qreg[t].z, qreg[t].w);
            uint32_t off = r * 128 + ((((qc >> 1) ^ (r & 7)) << 4) | ((qc & 1) << 3));
            asm volatile("st.shared.v2.b32 [%0], {%1, %2};" :: "r"(as + off), "r"(h0), "r"(h1) : "memory");
            if (match)
                *reinterpret_cast<float4*>(qo + (size_t)r * 1024 + qc * 4) = qreg[t];
        }
    };

    float d[2][8][4];
    #pragma unroll
    for (int i = 0; i < 2; i++)
        #pragma unroll
        for (int j = 0; j < 8; j++)
            #pragma unroll
            for (int k = 0; k < 4; k++) d[i][j][k] = 0.f;

    // one s-step of the compute block (ldmatrix + 16 MMAs)
    uint32_t as_cur, bs_cur;
    auto compute_s = [&](int s) {
        uint32_t a[2][4];
        #pragma unroll
        for (int mf = 0; mf < 2; mf++)
            ldm4(a[mf], as_cur + (rowA + mf * 16) * 128 + (((2 * s + hiA) ^ sw) << 4));
        #pragma unroll
        for (int p = 0; p < 4; p++) {
            uint32_t b[4];
            ldm4(b, bs_cur + (rowB + p * 16) * 128 + (((2 * s + hiB) ^ sw) << 4));
            mma16816(d[0][2 * p + 0], a[0], b[0], b[1]);
            mma16816(d[0][2 * p + 1], a[0], b[2], b[3]);
            mma16816(d[1][2 * p + 0], a[1], b[0], b[1]);
            mma16816(d[1][2 * p + 1], a[1], b[2], b[3]);
        }
    };

    // ---- prologue (exposed LDG->STS latency paid once)
    issueB(0); issueB(1);
    ldgQ(0, 0); stsA(0, 0);
    ldgQ(0, 1); stsA(0, 1);
    ldgQ(1, 0);                                              // bank holds (1, h0)

    for (int kc = 0; kc < NKC; kc++) {
        asm volatile("cp.async.wait_group 1;" ::: "memory"); // B chunk kc landed
        __syncthreads();                                     // A(kc) visible; stages fenced

        if (kc + 2 < NKC) issueB(kc + 2);
        else asm volatile("cp.async.commit_group;" ::: "memory");

        // A-relay first half: store (kc+1, h0), prefetch (kc+1, h1)
        if (kc + 1 < NKC) {
            stsA(kc + 1, 0);
            ldgQ(kc + 1, 1);
        }

        as_cur = sA + (kc & 1) * STAGE_BYTES;
        bs_cur = sB + (kc % 3) * STAGE_BYTES;
        compute_s(0);
        compute_s(1);

        // A-relay second half: store (kc+1, h1), prefetch (kc+2, h0)
        if (kc + 1 < NKC) {
            stsA(kc + 1, 1);
            if (kc + 2 < NKC) ldgQ(kc + 2, 0);
        }

        compute_s(2);
        compute_s(3);
    }

    // ---- epilogue: out[:, n0 + c] = p + pterm
    #pragma unroll
    for (int mf = 0; mf < 2; mf++) {
        #pragma unroll
        for (int rh = 0; rh < 2; rh++) {
            int row = m0 + wm * 32 + mf * 16 + rh * 8 + l4;
            const float* pr = pq + (size_t)row * 1024 + n0 + wn * 64 + 2 * lc;
            float* orow = out + (size_t)row * 1024 + n0 + wn * 64 + 2 * lc;
            #pragma unroll
            for (int nf = 0; nf < 8; nf++) {
                float2 pv = *reinterpret_cast<const float2*>(pr + nf * 8);
                float2 ov;
                ov.x = pv.x + d[mf][nf][rh * 2 + 0];
                ov.y = pv.y + d[mf][nf][rh * 2 + 1];
                *reinterpret_cast<float2*>(orow + nf * 8) = ov;
            }
        }
    }
}

extern "C" void kernel_launch(void* const* d_in, const int* in_sizes, int n_in,
                              void* d_out, int out_size) {
    const float* pq = (const float*)d_in[0];
    const float* A  = (const float*)d_in[1];
    if (n_in >= 2 && in_sizes[0] == DIM * DIM) {   // defensive: swap if order differs
        A  = (const float*)d_in[0];
        pq = (const float*)d_in[1];
    }
    float* out = (float*)d_out;

    cudaFuncSetAttribute(gemm_fused, cudaFuncAttributeMaxDynamicSharedMemorySize, SMEM_BYTES);
    prep_S<<<(DIM * DIM) / 256, 256>>>(A);
    gemm_fused<<<(65536 / TMt) * (DIM / TNt), 256, SMEM_BYTES>>>(pq, out);
}